// round 2
// baseline (speedup 1.0000x reference)
#include <cuda_runtime.h>
#include <math.h>

// Problem constants
#define BB 8
#define LL 2048
#define DD 1024
#define KS 32          // K (sensory)
#define JJ 512
#define T0V 2050       // 1 + L + 1
#define TSV 514        // 1 + J + 1
#define T1V 2082       // K + 1 + L + 1
#define SCALE 0.03125f // 1/sqrt(1024)

#define OUT0_ROWS 2016
#define OUT1_ROWS 2048
#define OFF1 ((long long)BB * OUT0_ROWS * DD)

// ------------------- scratch (__device__ globals, no allocation) -------------------
__device__ float g_X[BB * T1V * DD];
__device__ float g_Q[BB * T1V * DD];
__device__ float g_K[BB * T1V * DD];
__device__ float g_V[BB * T1V * DD];
__device__ float g_O[BB * T1V * DD];
__device__ float g_H[BB * T1V * DD];
__device__ float g_S[(long long)BB * T1V * T1V];
__device__ float g_M1[BB * DD];
__device__ float g_S1[BB * DD];
__device__ float g_Qn[BB * DD];
__device__ float g_Kp[BB * DD];
__device__ float g_P1[BB * DD];
__device__ float g_TA[BB * DD];
__device__ float g_TB[BB * DD];

// ------------------- tiled SGEMM: C = alpha * A @ op(B) + bias -------------------
// A: M x K row-major. TRANSB=false: B is K x N; TRANSB=true: B is N x K (C=A@B^T).
// Batched via gridDim.z with element strides sA/sB/sC.
#define BM 128
#define BN 128
#define BKK 8

template <bool TRANSB>
__global__ __launch_bounds__(256) void gemm_kernel(
    const float* __restrict__ A, const float* __restrict__ Bm,
    const float* __restrict__ bias, float* __restrict__ C,
    int M, int N, int Kd, float alpha,
    long long sA, long long sB, long long sC)
{
    A += (long long)blockIdx.z * sA;
    Bm += (long long)blockIdx.z * sB;
    C += (long long)blockIdx.z * sC;

    __shared__ float As[BKK][BM];
    __shared__ float Bs[BKK][BN];

    const int tid = threadIdx.x;
    const int tx = tid & 15;
    const int ty = tid >> 4;
    const int m0 = blockIdx.y * BM;
    const int n0 = blockIdx.x * BN;

    float acc[8][8];
#pragma unroll
    for (int i = 0; i < 8; i++)
#pragma unroll
        for (int j = 0; j < 8; j++) acc[i][j] = 0.f;

    for (int k0 = 0; k0 < Kd; k0 += BKK) {
        // Load A tile: 128 rows x 8 k, 4 elems/thread (same row, consecutive k)
#pragma unroll
        for (int i = 0; i < 4; i++) {
            int idx = tid * 4 + i;
            int m = idx >> 3, k = idx & 7;
            int gm = m0 + m, gk = k0 + k;
            As[k][m] = (gm < M && gk < Kd) ? A[(long long)gm * Kd + gk] : 0.f;
        }
        if (!TRANSB) {
#pragma unroll
            for (int i = 0; i < 4; i++) {
                int idx = tid * 4 + i;
                int k = idx >> 7, n = idx & 127;
                int gk = k0 + k, gn = n0 + n;
                Bs[k][n] = (gk < Kd && gn < N) ? Bm[(long long)gk * N + gn] : 0.f;
            }
        } else {
#pragma unroll
            for (int i = 0; i < 4; i++) {
                int idx = tid * 4 + i;
                int n = idx >> 3, k = idx & 7;
                int gn = n0 + n, gk = k0 + k;
                Bs[k][n] = (gn < N && gk < Kd) ? Bm[(long long)gn * Kd + gk] : 0.f;
            }
        }
        __syncthreads();

#pragma unroll
        for (int k = 0; k < BKK; k++) {
            float a[8], b[8];
            *(float4*)&a[0] = *(const float4*)&As[k][ty * 8];
            *(float4*)&a[4] = *(const float4*)&As[k][ty * 8 + 4];
            *(float4*)&b[0] = *(const float4*)&Bs[k][tx * 8];
            *(float4*)&b[4] = *(const float4*)&Bs[k][tx * 8 + 4];
#pragma unroll
            for (int i = 0; i < 8; i++)
#pragma unroll
                for (int j = 0; j < 8; j++)
                    acc[i][j] = fmaf(a[i], b[j], acc[i][j]);
        }
        __syncthreads();
    }

#pragma unroll
    for (int i = 0; i < 8; i++) {
        int gm = m0 + ty * 8 + i;
        if (gm >= M) continue;
#pragma unroll
        for (int j = 0; j < 8; j++) {
            int gn = n0 + tx * 8 + j;
            if (gn < N) {
                float v = alpha * acc[i][j];
                if (bias) v += bias[gn];
                C[(long long)gm * N + gn] = v;
            }
        }
    }
}

// ------------------- row softmax (register-resident, one pass) -------------------
__global__ __launch_bounds__(256) void softmax_rows_kernel(float* __restrict__ S, int Tk)
{
    long long row = blockIdx.x;
    float* r = S + row * (long long)Tk;
    int tid = threadIdx.x;
    __shared__ float red[256];

    float v[9];
    int cnt = 0;
    float mx = -1e30f;
    for (int i = tid; i < Tk; i += 256) {
        v[cnt] = r[i];
        mx = fmaxf(mx, v[cnt]);
        cnt++;
    }
    red[tid] = mx;
    __syncthreads();
    for (int s = 128; s > 0; s >>= 1) {
        if (tid < s) red[tid] = fmaxf(red[tid], red[tid + s]);
        __syncthreads();
    }
    mx = red[0];
    __syncthreads();

    float sum = 0.f;
    for (int c = 0; c < cnt; c++) {
        v[c] = __expf(v[c] - mx);
        sum += v[c];
    }
    red[tid] = sum;
    __syncthreads();
    for (int s = 128; s > 0; s >>= 1) {
        if (tid < s) red[tid] += red[tid + s];
        __syncthreads();
    }
    float inv = 1.f / red[0];

    cnt = 0;
    for (int i = tid; i < Tk; i += 256) r[i] = v[cnt++] * inv;
}

// ------------------- build inputs -------------------
__global__ void build_x0_kernel(float* __restrict__ X, const float* __restrict__ seg0)
{
    long long idx = (long long)blockIdx.x * blockDim.x + threadIdx.x;
    if (idx >= (long long)BB * T0V * DD) return;
    int d = (int)(idx & (DD - 1));
    long long r = idx >> 10;
    int t = (int)(r % T0V);
    int b = (int)(r / T0V);
    float v = 0.f;
    if (t >= 1 && t <= LL) v = seg0[((long long)b * LL + (t - 1)) * DD + d];
    X[idx] = v;
}

__global__ void build_xs_kernel(float* __restrict__ X, const float* __restrict__ seg1,
                                const float* __restrict__ prompt)
{
    long long idx = (long long)blockIdx.x * blockDim.x + threadIdx.x;
    if (idx >= (long long)BB * TSV * DD) return;
    int d = (int)(idx & (DD - 1));
    long long r = idx >> 10;
    int t = (int)(r % TSV);
    int b = (int)(r / TSV);
    float v;
    if (t == 0 || t == TSV - 1) v = prompt[d];
    else v = seg1[((long long)b * LL + (t - 1)) * DD + d];
    X[idx] = v;
}

__global__ void build_x1_kernel(float* __restrict__ X, const float* __restrict__ seg0,
                                const float* __restrict__ seg1, const float* __restrict__ P1)
{
    long long idx = (long long)blockIdx.x * blockDim.x + threadIdx.x;
    if (idx >= (long long)BB * T1V * DD) return;
    int d = (int)(idx & (DD - 1));
    long long r = idx >> 10;
    int t = (int)(r % T1V);
    int b = (int)(r / T1V);
    float v;
    if (t < KS) v = seg0[((long long)b * LL + (LL - KS + t)) * DD + d];
    else if (t == KS || t == T1V - 1) v = P1[b * DD + d];
    else v = seg1[((long long)b * LL + (t - KS - 1)) * DD + d];
    X[idx] = v;
}

// gather seg1[:, J-1, :] (content of summarize-query row) -> (B, D)
__global__ void gather_q_kernel(float* __restrict__ dst, const float* __restrict__ seg1)
{
    int idx = blockIdx.x * blockDim.x + threadIdx.x;
    if (idx >= BB * DD) return;
    int d = idx & (DD - 1);
    int b = idx >> 10;
    dst[idx] = seg1[((long long)b * LL + (JJ - 1)) * DD + d];
}

// copy rows [t_begin, t_begin+rows) of H (B, T, D) into dst (B, rows, D)
__global__ void copy_rows_kernel(float* __restrict__ dst, const float* __restrict__ H,
                                 int T, int t_begin, int rows)
{
    long long idx = (long long)blockIdx.x * blockDim.x + threadIdx.x;
    if (idx >= (long long)BB * rows * DD) return;
    int d = (int)(idx & (DD - 1));
    long long r = idx >> 10;
    int t = (int)(r % rows);
    int b = (int)(r / rows);
    dst[idx] = H[((long long)b * T + t_begin + t) * DD + d];
}

// ------------------- summarize attention: 1 query per batch, T keys -------------------
__global__ __launch_bounds__(256) void summ_attn_kernel(
    const float* __restrict__ Qrow, const float* __restrict__ Ksm,
    const float* __restrict__ Vsm, float* __restrict__ out, int T)
{
    int b = blockIdx.x;
    const float* q = Qrow + b * DD;
    const float* Kb = Ksm + (long long)b * T * DD;
    const float* Vb = Vsm + (long long)b * T * DD;
    __shared__ float sc[TSV];
    __shared__ float red[256];
    int tid = threadIdx.x;
    int lane = tid & 31, warp = tid >> 5;

    for (int j = warp; j < T; j += 8) {
        float s = 0.f;
        const float* kr = Kb + (long long)j * DD;
        for (int d = lane; d < DD; d += 32) s += q[d] * kr[d];
        for (int o = 16; o > 0; o >>= 1) s += __shfl_xor_sync(0xFFFFFFFFu, s, o);
        if (lane == 0) sc[j] = s * SCALE;
    }
    __syncthreads();

    float mx = -1e30f;
    for (int i = tid; i < T; i += 256) mx = fmaxf(mx, sc[i]);
    red[tid] = mx;
    __syncthreads();
    for (int s = 128; s > 0; s >>= 1) {
        if (tid < s) red[tid] = fmaxf(red[tid], red[tid + s]);
        __syncthreads();
    }
    mx = red[0];
    __syncthreads();

    float sum = 0.f;
    for (int i = tid; i < T; i += 256) {
        float e = __expf(sc[i] - mx);
        sc[i] = e;
        sum += e;
    }
    red[tid] = sum;
    __syncthreads();
    for (int s = 128; s > 0; s >>= 1) {
        if (tid < s) red[tid] += red[tid + s];
        __syncthreads();
    }
    float inv = 1.f / red[0];
    __syncthreads();
    for (int i = tid; i < T; i += 256) sc[i] *= inv;
    __syncthreads();

    for (int d = tid; d < DD; d += 256) {
        float acc = 0.f;
        for (int j = 0; j < T; j++) acc = fmaf(sc[j], Vb[(long long)j * DD + d], acc);
        out[b * DD + d] = acc;
    }
}

// ------------------- memory attention: (B,1,D) x (B,D) -> (B,D), 8x8 scores -------------------
__global__ __launch_bounds__(256) void mem_attn_kernel(
    const float* __restrict__ Qn, const float* __restrict__ Kp,
    const float* __restrict__ M1, float* __restrict__ P1)
{
    __shared__ float sc[BB][BB];
    int tid = threadIdx.x;
    int lane = tid & 31, warp = tid >> 5;

    // 8 warps: warp w computes score row w (8 dots of length D)
    for (int j = 0; j < BB; j++) {
        float s = 0.f;
        for (int d = lane; d < DD; d += 32) s += Qn[warp * DD + d] * Kp[j * DD + d];
        for (int o = 16; o > 0; o >>= 1) s += __shfl_xor_sync(0xFFFFFFFFu, s, o);
        if (lane == 0) sc[warp][j] = s * SCALE;
    }
    __syncthreads();

    if (tid < BB) {
        float mx = -1e30f;
        for (int j = 0; j < BB; j++) mx = fmaxf(mx, sc[tid][j]);
        float sum = 0.f;
        for (int j = 0; j < BB; j++) {
            float e = __expf(sc[tid][j] - mx);
            sc[tid][j] = e;
            sum += e;
        }
        float inv = 1.f / sum;
        for (int j = 0; j < BB; j++) sc[tid][j] *= inv;
    }
    __syncthreads();

    for (int idx = tid; idx < BB * DD; idx += 256) {
        int b = idx >> 10, d = idx & (DD - 1);
        float acc = 0.f;
        for (int j = 0; j < BB; j++) acc = fmaf(sc[b][j], M1[j * DD + d], acc);
        P1[idx] = acc;
    }
}

// ------------------- host orchestration -------------------
static inline void gemm(const float* A, const float* Bm, const float* bias, float* C,
                        int M, int N, int Kd, float alpha, int batch,
                        long long sA, long long sB, long long sC, bool transB)
{
    dim3 grid((N + BN - 1) / BN, (M + BM - 1) / BM, batch);
    if (transB)
        gemm_kernel<true><<<grid, 256>>>(A, Bm, bias, C, M, N, Kd, alpha, sA, sB, sC);
    else
        gemm_kernel<false><<<grid, 256>>>(A, Bm, bias, C, M, N, Kd, alpha, sA, sB, sC);
}

extern "C" void kernel_launch(void* const* d_in, const int* in_sizes, int n_in,
                              void* d_out, int out_size)
{
    const float* seg0   = (const float*)d_in[0];
    const float* seg1   = (const float*)d_in[1];
    const float* prompt = (const float*)d_in[2];
    const float* Wq_mem = (const float*)d_in[3];
    const float* bq_mem = (const float*)d_in[4];
    const float* Wk_mem = (const float*)d_in[5];
    const float* bk_mem = (const float*)d_in[6];
    const float* Wq     = (const float*)d_in[7];
    const float* bq     = (const float*)d_in[8];
    const float* Wk     = (const float*)d_in[9];
    const float* bk     = (const float*)d_in[10];
    const float* Wv     = (const float*)d_in[11];
    const float* bv     = (const float*)d_in[12];
    const float* Wo     = (const float*)d_in[13];
    const float* bo     = (const float*)d_in[14];
    float* out = (float*)d_out;

    float *pX, *pQ, *pK, *pV, *pO, *pH, *pS;
    float *pM1, *pS1, *pQn, *pKp, *pP1, *pTA, *pTB;
    cudaGetSymbolAddress((void**)&pX, g_X);
    cudaGetSymbolAddress((void**)&pQ, g_Q);
    cudaGetSymbolAddress((void**)&pK, g_K);
    cudaGetSymbolAddress((void**)&pV, g_V);
    cudaGetSymbolAddress((void**)&pO, g_O);
    cudaGetSymbolAddress((void**)&pH, g_H);
    cudaGetSymbolAddress((void**)&pS, g_S);
    cudaGetSymbolAddress((void**)&pM1, g_M1);
    cudaGetSymbolAddress((void**)&pS1, g_S1);
    cudaGetSymbolAddress((void**)&pQn, g_Qn);
    cudaGetSymbolAddress((void**)&pKp, g_Kp);
    cudaGetSymbolAddress((void**)&pP1, g_P1);
    cudaGetSymbolAddress((void**)&pTA, g_TA);
    cudaGetSymbolAddress((void**)&pTB, g_TB);

    const int nthr = 256;

    // ---------------- Phase 0: backbone over [0, seg0, 0], T = 2050 ----------------
    {
        long long n = (long long)BB * T0V * DD;
        build_x0_kernel<<<(int)((n + nthr - 1) / nthr), nthr>>>(pX, seg0);

        int M = BB * T0V;
        gemm(pX, Wq, bq, pQ, M, DD, DD, 1.f, 1, 0, 0, 0, false);
        gemm(pX, Wk, bk, pK, M, DD, DD, 1.f, 1, 0, 0, 0, false);
        gemm(pX, Wv, bv, pV, M, DD, DD, 1.f, 1, 0, 0, 0, false);

        // scores S = Q @ K^T * scale (batched over B)
        gemm(pQ, pK, nullptr, pS, T0V, T0V, DD, SCALE, BB,
             (long long)T0V * DD, (long long)T0V * DD, (long long)T0V * T0V, true);
        softmax_rows_kernel<<<BB * T0V, 256>>>(pS, T0V);
        // O = P @ V
        gemm(pS, pV, nullptr, pO, T0V, DD, T0V, 1.f, BB,
             (long long)T0V * T0V, (long long)T0V * DD, (long long)T0V * DD, false);
        // H = O @ Wo + bo
        gemm(pO, Wo, bo, pH, M, DD, DD, 1.f, 1, 0, 0, 0, false);

        // out0 = H rows 33..2048 ; M1 = H row 2049
        long long n0 = (long long)BB * OUT0_ROWS * DD;
        copy_rows_kernel<<<(int)((n0 + nthr - 1) / nthr), nthr>>>(out, pH, T0V, KS + 1, OUT0_ROWS);
        copy_rows_kernel<<<(BB * DD + nthr - 1) / nthr, nthr>>>(pM1, pH, T0V, T0V - 1, 1);
    }

    // ---------------- Summarize(seg1): T = 514, only query row J needed ----------------
    {
        long long n = (long long)BB * TSV * DD;
        build_xs_kernel<<<(int)((n + nthr - 1) / nthr), nthr>>>(pX, seg1, prompt);

        int M = BB * TSV;
        gemm(pX, Wk, bk, pK, M, DD, DD, 1.f, 1, 0, 0, 0, false);
        gemm(pX, Wv, bv, pV, M, DD, DD, 1.f, 1, 0, 0, 0, false);

        gather_q_kernel<<<(BB * DD + nthr - 1) / nthr, nthr>>>(pTA, seg1);
        gemm(pTA, Wq, bq, pTB, BB, DD, DD, 1.f, 1, 0, 0, 0, false); // q rows (B, D)

        summ_attn_kernel<<<BB, 256>>>(pTB, pK, pV, pTA, TSV);       // attn out (B, D)
        gemm(pTA, Wo, bo, pS1, BB, DD, DD, 1.f, 1, 0, 0, 0, false); // S1
    }

    // ---------------- Memory attention ----------------
    {
        gemm(pS1, Wq_mem, bq_mem, pQn, BB, DD, DD, 1.f, 1, 0, 0, 0, false);
        gemm(pM1, Wk_mem, bk_mem, pKp, BB, DD, DD, 1.f, 1, 0, 0, 0, false);
        mem_attn_kernel<<<1, 256>>>(pQn, pKp, pM1, pP1);
    }

    // ---------------- Phase 1: backbone over [sensory, P1, seg1, P1], T = 2082 ----------------
    {
        long long n = (long long)BB * T1V * DD;
        build_x1_kernel<<<(int)((n + nthr - 1) / nthr), nthr>>>(pX, seg0, seg1, pP1);

        int M = BB * T1V;
        gemm(pX, Wq, bq, pQ, M, DD, DD, 1.f, 1, 0, 0, 0, false);
        gemm(pX, Wk, bk, pK, M, DD, DD, 1.f, 1, 0, 0, 0, false);
        gemm(pX, Wv, bv, pV, M, DD, DD, 1.f, 1, 0, 0, 0, false);

        gemm(pQ, pK, nullptr, pS, T1V, T1V, DD, SCALE, BB,
             (long long)T1V * DD, (long long)T1V * DD, (long long)T1V * T1V, true);
        softmax_rows_kernel<<<BB * T1V, 256>>>(pS, T1V);
        gemm(pS, pV, nullptr, pO, T1V, DD, T1V, 1.f, BB,
             (long long)T1V * T1V, (long long)T1V * DD, (long long)T1V * DD, false);
        gemm(pO, Wo, bo, pH, M, DD, DD, 1.f, 1, 0, 0, 0, false);

        long long n1 = (long long)BB * OUT1_ROWS * DD;
        copy_rows_kernel<<<(int)((n1 + nthr - 1) / nthr), nthr>>>(out + OFF1, pH, T1V, KS + 1, OUT1_ROWS);
    }
}

// round 6
// speedup vs baseline: 4.7330x; 4.7330x over previous
#include <cuda_runtime.h>
#include <math.h>

// Problem constants
#define BB 8
#define LL 2048
#define DD 1024
#define KS 32
#define JJ 512
#define T0V 2050
#define TSV 514
#define T1V 2082
#define SCALE 0.03125f

// padded score pitches (multiple of 4 floats -> 16B-aligned rows)
#define SP0 2052
#define SP1 2084

#define OUT0_ROWS 2016
#define OUT1_ROWS 2048
#define OFF1 ((long long)BB * OUT0_ROWS * DD)

// ------------------- scratch -------------------
__device__ float g_X[BB * T1V * DD];
__device__ float g_Q[BB * T1V * DD];
__device__ float g_K[BB * T1V * DD];
__device__ float g_V[BB * T1V * DD];
__device__ float g_O[BB * T1V * DD];
__device__ float g_H[BB * T1V * DD];
__device__ float g_S[(long long)BB * T1V * SP1];
__device__ float g_M1[BB * DD];
__device__ float g_S1[BB * DD];
__device__ float g_Qn[BB * DD];
__device__ float g_Kp[BB * DD];
__device__ float g_P1[BB * DD];
__device__ float g_TA[BB * DD];
__device__ float g_TB[BB * DD];

// ------------------- TF32 tensor-core GEMM -------------------
// C = alpha * A @ op(B) + bias.  A: MxK row-major (pitch lda).
// TRANSB=false: B is KxN (pitch ldb).  TRANSB=true: B is NxK (pitch ldb), C = A@B^T.
// Block tile 128x128, k-tile 32, 8 warps, warp tile 64x32,
// mma.sync.m16n8k8.tf32, cp.async double-buffered.
// NOTE: all of lda/ldb/ldc and the base pointers must be 16-byte aligned
// (lda/ldb multiples of 4 floats) because of cp.async.cg 16B loads.
#define APITCH 36
#define BPITCH_NN 136
#define AS_FLOATS (128 * APITCH)
#define BS_FLOATS (128 * APITCH)
#define STAGE_FLOATS (AS_FLOATS + BS_FLOATS)
#define GEMM_SMEM_BYTES (2 * STAGE_FLOATS * 4)   // 73728

__device__ __forceinline__ unsigned f2tf(float x) {
    unsigned r;
    asm("cvt.rna.tf32.f32 %0, %1;" : "=r"(r) : "f"(x));
    return r;
}

__device__ __forceinline__ void mma_tf32(float (&c)[4], unsigned a0, unsigned a1,
                                         unsigned a2, unsigned a3, unsigned b0, unsigned b1) {
    asm volatile(
        "mma.sync.aligned.m16n8k8.row.col.f32.tf32.tf32.f32 "
        "{%0,%1,%2,%3}, {%4,%5,%6,%7}, {%8,%9}, {%0,%1,%2,%3};"
        : "+f"(c[0]), "+f"(c[1]), "+f"(c[2]), "+f"(c[3])
        : "r"(a0), "r"(a1), "r"(a2), "r"(a3), "r"(b0), "r"(b1));
}

__device__ __forceinline__ void cp_async16(float* s, const float* g, int bytes) {
    unsigned saddr = (unsigned)__cvta_generic_to_shared(s);
    asm volatile("cp.async.cg.shared.global [%0], [%1], 16, %2;\n"
                 :: "r"(saddr), "l"(g), "r"(bytes));
}

template <bool TRANSB>
__global__ __launch_bounds__(256, 2) void gemm_tf32_kernel(
    const float* __restrict__ A, const float* __restrict__ Bm,
    const float* __restrict__ bias, float* __restrict__ C,
    int M, int N, int Kd, float alpha,
    int lda, int ldb, int ldc,
    long long sA, long long sB, long long sC)
{
    A += (long long)blockIdx.z * sA;
    Bm += (long long)blockIdx.z * sB;
    C += (long long)blockIdx.z * sC;

    extern __shared__ float smem[];
    const int tid = threadIdx.x;
    const int warp = tid >> 5;
    const int lane = tid & 31;
    const int warp_m = warp & 1;
    const int warp_n = warp >> 1;
    const int qrow = lane >> 2;
    const int qcol = lane & 3;
    const int m0 = blockIdx.y * 128;
    const int n0 = blockIdx.x * 128;

    float acc[16][4];
#pragma unroll
    for (int i = 0; i < 16; i++)
#pragma unroll
        for (int j = 0; j < 4; j++) acc[i][j] = 0.f;

    const int nk = (Kd + 31) >> 5;

    auto load_tiles = [&](int kt, int buf) {
        float* As = smem + buf * STAGE_FLOATS;
        float* Bs = As + AS_FLOATS;
        int k0 = kt << 5;
#pragma unroll
        for (int c = 0; c < 4; c++) {
            int idx = c * 256 + tid;
            int m = idx >> 3, k4 = (idx & 7) << 2;
            int gm = m0 + m, gk = k0 + k4;
            int rem = Kd - gk;
            int bytes = (gm < M) ? (rem >= 4 ? 16 : (rem > 0 ? rem * 4 : 0)) : 0;
            const float* src = bytes ? (A + (long long)gm * lda + gk) : A;
            cp_async16(As + m * APITCH + k4, src, bytes);
        }
        if (!TRANSB) {
#pragma unroll
            for (int c = 0; c < 4; c++) {
                int idx = c * 256 + tid;
                int k = idx >> 5, n4 = (idx & 31) << 2;
                int gk = k0 + k, gn = n0 + n4;
                int rem = N - gn;
                int bytes = (gk < Kd) ? (rem >= 4 ? 16 : (rem > 0 ? rem * 4 : 0)) : 0;
                const float* src = bytes ? (Bm + (long long)gk * ldb + gn) : Bm;
                cp_async16(Bs + k * BPITCH_NN + n4, src, bytes);
            }
        } else {
#pragma unroll
            for (int c = 0; c < 4; c++) {
                int idx = c * 256 + tid;
                int n = idx >> 3, k4 = (idx & 7) << 2;
                int gn = n0 + n, gk = k0 + k4;
                int rem = Kd - gk;
                int bytes = (gn < N) ? (rem >= 4 ? 16 : (rem > 0 ? rem * 4 : 0)) : 0;
                const float* src = bytes ? (Bm + (long long)gn * ldb + gk) : Bm;
                cp_async16(Bs + n * APITCH + k4, src, bytes);
            }
        }
        asm volatile("cp.async.commit_group;\n");
    };

    load_tiles(0, 0);

    for (int kt = 0; kt < nk; kt++) {
        if (kt + 1 < nk) {
            load_tiles(kt + 1, (kt + 1) & 1);
            asm volatile("cp.async.wait_group 1;\n");
        } else {
            asm volatile("cp.async.wait_group 0;\n");
        }
        __syncthreads();

        const float* As = smem + (kt & 1) * STAGE_FLOATS;
        const float* Bs = As + AS_FLOATS;

#pragma unroll
        for (int kk = 0; kk < 32; kk += 8) {
            unsigned af[4][4], bf[4][2];
#pragma unroll
            for (int mt = 0; mt < 4; mt++) {
                const float* ap = As + (warp_m * 64 + mt * 16 + qrow) * APITCH + kk + qcol;
                af[mt][0] = f2tf(ap[0]);
                af[mt][1] = f2tf(ap[8 * APITCH]);
                af[mt][2] = f2tf(ap[4]);
                af[mt][3] = f2tf(ap[8 * APITCH + 4]);
            }
#pragma unroll
            for (int nt = 0; nt < 4; nt++) {
                int n = warp_n * 32 + nt * 8 + qrow;
                if (!TRANSB) {
                    const float* bp = Bs + (kk + qcol) * BPITCH_NN + n;
                    bf[nt][0] = f2tf(bp[0]);
                    bf[nt][1] = f2tf(bp[4 * BPITCH_NN]);
                } else {
                    const float* bp = Bs + n * APITCH + kk + qcol;
                    bf[nt][0] = f2tf(bp[0]);
                    bf[nt][1] = f2tf(bp[4]);
                }
            }
#pragma unroll
            for (int mt = 0; mt < 4; mt++)
#pragma unroll
                for (int nt = 0; nt < 4; nt++)
                    mma_tf32(acc[mt * 4 + nt], af[mt][0], af[mt][1], af[mt][2], af[mt][3],
                             bf[nt][0], bf[nt][1]);
        }
        __syncthreads();
    }

#pragma unroll
    for (int mt = 0; mt < 4; mt++) {
#pragma unroll
        for (int nt = 0; nt < 4; nt++) {
            float* c = acc[mt * 4 + nt];
            int gm = m0 + warp_m * 64 + mt * 16 + qrow;
            int gn = n0 + warp_n * 32 + nt * 8 + (qcol << 1);
            float bx = 0.f, by = 0.f;
            if (bias && gn < N) { bx = bias[gn]; by = bias[gn + 1]; }
            if (gm < M && gn < N) {
                float2 v = make_float2(alpha * c[0] + bx, alpha * c[1] + by);
                *(float2*)(C + (long long)gm * ldc + gn) = v;
            }
            if (gm + 8 < M && gn < N) {
                float2 v = make_float2(alpha * c[2] + bx, alpha * c[3] + by);
                *(float2*)(C + (long long)(gm + 8) * ldc + gn) = v;
            }
        }
    }
}

// ------------------- row softmax (pitched) -------------------
__global__ __launch_bounds__(256) void softmax_rows_kernel(float* __restrict__ S, int Tk, int pitch)
{
    long long row = blockIdx.x;
    float* r = S + row * (long long)pitch;
    int tid = threadIdx.x;
    __shared__ float red[256];

    float v[9];
    int cnt = 0;
    float mx = -1e30f;
    for (int i = tid; i < Tk; i += 256) {
        v[cnt] = r[i];
        mx = fmaxf(mx, v[cnt]);
        cnt++;
    }
    red[tid] = mx;
    __syncthreads();
    for (int s = 128; s > 0; s >>= 1) {
        if (tid < s) red[tid] = fmaxf(red[tid], red[tid + s]);
        __syncthreads();
    }
    mx = red[0];
    __syncthreads();

    float sum = 0.f;
    for (int c = 0; c < cnt; c++) {
        v[c] = __expf(v[c] - mx);
        sum += v[c];
    }
    red[tid] = sum;
    __syncthreads();
    for (int s = 128; s > 0; s >>= 1) {
        if (tid < s) red[tid] += red[tid + s];
        __syncthreads();
    }
    float inv = 1.f / red[0];

    cnt = 0;
    for (int i = tid; i < Tk; i += 256) r[i] = v[cnt++] * inv;
}

// ------------------- build inputs -------------------
__global__ void build_x0_kernel(float* __restrict__ X, const float* __restrict__ seg0)
{
    long long idx = (long long)blockIdx.x * blockDim.x + threadIdx.x;
    if (idx >= (long long)BB * T0V * DD) return;
    int d = (int)(idx & (DD - 1));
    long long r = idx >> 10;
    int t = (int)(r % T0V);
    int b = (int)(r / T0V);
    float v = 0.f;
    if (t >= 1 && t <= LL) v = seg0[((long long)b * LL + (t - 1)) * DD + d];
    X[idx] = v;
}

__global__ void build_xs_kernel(float* __restrict__ X, const float* __restrict__ seg1,
                                const float* __restrict__ prompt)
{
    long long idx = (long long)blockIdx.x * blockDim.x + threadIdx.x;
    if (idx >= (long long)BB * TSV * DD) return;
    int d = (int)(idx & (DD - 1));
    long long r = idx >> 10;
    int t = (int)(r % TSV);
    int b = (int)(r / TSV);
    float v;
    if (t == 0 || t == TSV - 1) v = prompt[d];
    else v = seg1[((long long)b * LL + (t - 1)) * DD + d];
    X[idx] = v;
}

__global__ void build_x1_kernel(float* __restrict__ X, const float* __restrict__ seg0,
                                const float* __restrict__ seg1, const float* __restrict__ P1)
{
    long long idx = (long long)blockIdx.x * blockDim.x + threadIdx.x;
    if (idx >= (long long)BB * T1V * DD) return;
    int d = (int)(idx & (DD - 1));
    long long r = idx >> 10;
    int t = (int)(r % T1V);
    int b = (int)(r / T1V);
    float v;
    if (t < KS) v = seg0[((long long)b * LL + (LL - KS + t)) * DD + d];
    else if (t == KS || t == T1V - 1) v = P1[b * DD + d];
    else v = seg1[((long long)b * LL + (t - KS - 1)) * DD + d];
    X[idx] = v;
}

__global__ void gather_q_kernel(float* __restrict__ dst, const float* __restrict__ seg1)
{
    int idx = blockIdx.x * blockDim.x + threadIdx.x;
    if (idx >= BB * DD) return;
    int d = idx & (DD - 1);
    int b = idx >> 10;
    dst[idx] = seg1[((long long)b * LL + (JJ - 1)) * DD + d];
}

__global__ void copy_rows_kernel(float* __restrict__ dst, const float* __restrict__ H,
                                 int T, int t_begin, int rows)
{
    long long idx = (long long)blockIdx.x * blockDim.x + threadIdx.x;
    if (idx >= (long long)BB * rows * DD) return;
    int d = (int)(idx & (DD - 1));
    long long r = idx >> 10;
    int t = (int)(r % rows);
    int b = (int)(r / rows);
    dst[idx] = H[((long long)b * T + t_begin + t) * DD + d];
}

// ------------------- summarize attention -------------------
__global__ __launch_bounds__(256) void summ_attn_kernel(
    const float* __restrict__ Qrow, const float* __restrict__ Ksm,
    const float* __restrict__ Vsm, float* __restrict__ out, int T)
{
    int b = blockIdx.x;
    const float* q = Qrow + b * DD;
    const float* Kb = Ksm + (long long)b * T * DD;
    const float* Vb = Vsm + (long long)b * T * DD;
    __shared__ float sc[TSV];
    __shared__ float red[256];
    int tid = threadIdx.x;
    int lane = tid & 31, warp = tid >> 5;

    for (int j = warp; j < T; j += 8) {
        float s = 0.f;
        const float* kr = Kb + (long long)j * DD;
        for (int d = lane; d < DD; d += 32) s += q[d] * kr[d];
        for (int o = 16; o > 0; o >>= 1) s += __shfl_xor_sync(0xFFFFFFFFu, s, o);
        if (lane == 0) sc[j] = s * SCALE;
    }
    __syncthreads();

    float mx = -1e30f;
    for (int i = tid; i < T; i += 256) mx = fmaxf(mx, sc[i]);
    red[tid] = mx;
    __syncthreads();
    for (int s = 128; s > 0; s >>= 1) {
        if (tid < s) red[tid] = fmaxf(red[tid], red[tid + s]);
        __syncthreads();
    }
    mx = red[0];
    __syncthreads();

    float sum = 0.f;
    for (int i = tid; i < T; i += 256) {
        float e = __expf(sc[i] - mx);
        sc[i] = e;
        sum += e;
    }
    red[tid] = sum;
    __syncthreads();
    for (int s = 128; s > 0; s >>= 1) {
        if (tid < s) red[tid] += red[tid + s];
        __syncthreads();
    }
    float inv = 1.f / red[0];
    __syncthreads();
    for (int i = tid; i < T; i += 256) sc[i] *= inv;
    __syncthreads();

    for (int d = tid; d < DD; d += 256) {
        float acc = 0.f;
        for (int j = 0; j < T; j++) acc = fmaf(sc[j], Vb[(long long)j * DD + d], acc);
        out[b * DD + d] = acc;
    }
}

// ------------------- memory attention -------------------
__global__ __launch_bounds__(256) void mem_attn_kernel(
    const float* __restrict__ Qn, const float* __restrict__ Kp,
    const float* __restrict__ M1, float* __restrict__ P1)
{
    __shared__ float sc[BB][BB];
    int tid = threadIdx.x;
    int lane = tid & 31, warp = tid >> 5;

    for (int j = 0; j < BB; j++) {
        float s = 0.f;
        for (int d = lane; d < DD; d += 32) s += Qn[warp * DD + d] * Kp[j * DD + d];
        for (int o = 16; o > 0; o >>= 1) s += __shfl_xor_sync(0xFFFFFFFFu, s, o);
        if (lane == 0) sc[warp][j] = s * SCALE;
    }
    __syncthreads();

    if (tid < BB) {
        float mx = -1e30f;
        for (int j = 0; j < BB; j++) mx = fmaxf(mx, sc[tid][j]);
        float sum = 0.f;
        for (int j = 0; j < BB; j++) {
            float e = __expf(sc[tid][j] - mx);
            sc[tid][j] = e;
            sum += e;
        }
        float inv = 1.f / sum;
        for (int j = 0; j < BB; j++) sc[tid][j] *= inv;
    }
    __syncthreads();

    for (int idx = tid; idx < BB * DD; idx += 256) {
        int b = idx >> 10, d = idx & (DD - 1);
        float acc = 0.f;
        for (int j = 0; j < BB; j++) acc = fmaf(sc[b][j], M1[j * DD + d], acc);
        P1[idx] = acc;
    }
}

// ------------------- host orchestration -------------------
static inline void gemm(const float* A, const float* Bm, const float* bias, float* C,
                        int M, int N, int Kd, float alpha, int batch,
                        long long sA, long long sB, long long sC, bool transB,
                        int lda, int ldb, int ldc)
{
    dim3 grid((N + 127) / 128, (M + 127) / 128, batch);
    if (transB) {
        cudaFuncSetAttribute(gemm_tf32_kernel<true>,
                             cudaFuncAttributeMaxDynamicSharedMemorySize, GEMM_SMEM_BYTES);
        gemm_tf32_kernel<true><<<grid, 256, GEMM_SMEM_BYTES>>>(A, Bm, bias, C, M, N, Kd, alpha,
                                                               lda, ldb, ldc, sA, sB, sC);
    } else {
        cudaFuncSetAttribute(gemm_tf32_kernel<false>,
                             cudaFuncAttributeMaxDynamicSharedMemorySize, GEMM_SMEM_BYTES);
        gemm_tf32_kernel<false><<<grid, 256, GEMM_SMEM_BYTES>>>(A, Bm, bias, C, M, N, Kd, alpha,
                                                                lda, ldb, ldc, sA, sB, sC);
    }
}

extern "C" void kernel_launch(void* const* d_in, const int* in_sizes, int n_in,
                              void* d_out, int out_size)
{
    const float* seg0   = (const float*)d_in[0];
    const float* seg1   = (const float*)d_in[1];
    const float* prompt = (const float*)d_in[2];
    const float* Wq_mem = (const float*)d_in[3];
    const float* bq_mem = (const float*)d_in[4];
    const float* Wk_mem = (const float*)d_in[5];
    const float* bk_mem = (const float*)d_in[6];
    const float* Wq     = (const float*)d_in[7];
    const float* bq     = (const float*)d_in[8];
    const float* Wk     = (const float*)d_in[9];
    const float* bk     = (const float*)d_in[10];
    const float* Wv     = (const float*)d_in[11];
    const float* bv     = (const float*)d_in[12];
    const float* Wo     = (const float*)d_in[13];
    const float* bo     = (const float*)d_in[14];
    float* out = (float*)d_out;

    float *pX, *pQ, *pK, *pV, *pO, *pH, *pS;
    float *pM1, *pS1, *pQn, *pKp, *pP1, *pTA, *pTB;
    cudaGetSymbolAddress((void**)&pX, g_X);
    cudaGetSymbolAddress((void**)&pQ, g_Q);
    cudaGetSymbolAddress((void**)&pK, g_K);
    cudaGetSymbolAddress((void**)&pV, g_V);
    cudaGetSymbolAddress((void**)&pO, g_O);
    cudaGetSymbolAddress((void**)&pH, g_H);
    cudaGetSymbolAddress((void**)&pS, g_S);
    cudaGetSymbolAddress((void**)&pM1, g_M1);
    cudaGetSymbolAddress((void**)&pS1, g_S1);
    cudaGetSymbolAddress((void**)&pQn, g_Qn);
    cudaGetSymbolAddress((void**)&pKp, g_Kp);
    cudaGetSymbolAddress((void**)&pP1, g_P1);
    cudaGetSymbolAddress((void**)&pTA, g_TA);
    cudaGetSymbolAddress((void**)&pTB, g_TB);

    const int nthr = 256;

    // ---------------- Phase 0: backbone over [0, seg0, 0], T = 2050 ----------------
    {
        long long n = (long long)BB * T0V * DD;
        build_x0_kernel<<<(int)((n + nthr - 1) / nthr), nthr>>>(pX, seg0);

        int M = BB * T0V;
        gemm(pX, Wq, bq, pQ, M, DD, DD, 1.f, 1, 0, 0, 0, false, DD, DD, DD);
        gemm(pX, Wk, bk, pK, M, DD, DD, 1.f, 1, 0, 0, 0, false, DD, DD, DD);
        gemm(pX, Wv, bv, pV, M, DD, DD, 1.f, 1, 0, 0, 0, false, DD, DD, DD);

        gemm(pQ, pK, nullptr, pS, T0V, T0V, DD, SCALE, BB,
             (long long)T0V * DD, (long long)T0V * DD, (long long)T0V * SP0, true,
             DD, DD, SP0);
        softmax_rows_kernel<<<BB * T0V, 256>>>(pS, T0V, SP0);
        gemm(pS, pV, nullptr, pO, T0V, DD, T0V, 1.f, BB,
             (long long)T0V * SP0, (long long)T0V * DD, (long long)T0V * DD, false,
             SP0, DD, DD);
        gemm(pO, Wo, bo, pH, M, DD, DD, 1.f, 1, 0, 0, 0, false, DD, DD, DD);

        long long n0 = (long long)BB * OUT0_ROWS * DD;
        copy_rows_kernel<<<(int)((n0 + nthr - 1) / nthr), nthr>>>(out, pH, T0V, KS + 1, OUT0_ROWS);
        copy_rows_kernel<<<(BB * DD + nthr - 1) / nthr, nthr>>>(pM1, pH, T0V, T0V - 1, 1);
    }

    // ---------------- Summarize(seg1): T = 514 ----------------
    {
        long long n = (long long)BB * TSV * DD;
        build_xs_kernel<<<(int)((n + nthr - 1) / nthr), nthr>>>(pX, seg1, prompt);

        int M = BB * TSV;
        gemm(pX, Wk, bk, pK, M, DD, DD, 1.f, 1, 0, 0, 0, false, DD, DD, DD);
        gemm(pX, Wv, bv, pV, M, DD, DD, 1.f, 1, 0, 0, 0, false, DD, DD, DD);

        gather_q_kernel<<<(BB * DD + nthr - 1) / nthr, nthr>>>(pTA, seg1);
        gemm(pTA, Wq, bq, pTB, BB, DD, DD, 1.f, 1, 0, 0, 0, false, DD, DD, DD);

        summ_attn_kernel<<<BB, 256>>>(pTB, pK, pV, pTA, TSV);
        gemm(pTA, Wo, bo, pS1, BB, DD, DD, 1.f, 1, 0, 0, 0, false, DD, DD, DD);
    }

    // ---------------- Memory attention ----------------
    {
        gemm(pS1, Wq_mem, bq_mem, pQn, BB, DD, DD, 1.f, 1, 0, 0, 0, false, DD, DD, DD);
        gemm(pM1, Wk_mem, bk_mem, pKp, BB, DD, DD, 1.f, 1, 0, 0, 0, false, DD, DD, DD);
        mem_attn_kernel<<<1, 256>>>(pQn, pKp, pM1, pP1);
    }

    // ---------------- Phase 1: backbone over [sensory, P1, seg1, P1], T = 2082 ----------------
    {
        long long n = (long long)BB * T1V * DD;
        build_x1_kernel<<<(int)((n + nthr - 1) / nthr), nthr>>>(pX, seg0, seg1, pP1);

        int M = BB * T1V;
        gemm(pX, Wq, bq, pQ, M, DD, DD, 1.f, 1, 0, 0, 0, false, DD, DD, DD);
        gemm(pX, Wk, bk, pK, M, DD, DD, 1.f, 1, 0, 0, 0, false, DD, DD, DD);
        gemm(pX, Wv, bv, pV, M, DD, DD, 1.f, 1, 0, 0, 0, false, DD, DD, DD);

        gemm(pQ, pK, nullptr, pS, T1V, T1V, DD, SCALE, BB,
             (long long)T1V * DD, (long long)T1V * DD, (long long)T1V * SP1, true,
             DD, DD, SP1);
        softmax_rows_kernel<<<BB * T1V, 256>>>(pS, T1V, SP1);
        gemm(pS, pV, nullptr, pO, T1V, DD, T1V, 1.f, BB,
             (long long)T1V * SP1, (long long)T1V * DD, (long long)T1V * DD, false,
             SP1, DD, DD);
        gemm(pO, Wo, bo, pH, M, DD, DD, 1.f, 1, 0, 0, 0, false, DD, DD, DD);

        long long n1 = (long long)BB * OUT1_ROWS * DD;
        copy_rows_kernel<<<(int)((n1 + nthr - 1) / nthr), nthr>>>(out + OFF1, pH, T1V, KS + 1, OUT1_ROWS);
    }
}

// round 8
// speedup vs baseline: 5.2020x; 1.0991x over previous
#include <cuda_runtime.h>
#include <math.h>

// Problem constants
#define BB 8
#define LL 2048
#define DD 1024
#define KS 32
#define JJ 512
#define T0V 2050
#define TSV 514
#define T1V 2082
#define SCALE 0.03125f

// padded score pitches (multiple of 4 floats -> 16B-aligned rows)
#define SP0 2052
#define SP1 2084

#define OUT0_ROWS 2016
#define OUT1_ROWS 2048
#define OFF1 ((long long)BB * OUT0_ROWS * DD)

// ------------------- scratch -------------------
__device__ float g_X[BB * T1V * DD];
__device__ float g_Q[BB * T1V * DD];
__device__ float g_K[BB * T1V * DD];
__device__ float g_V[BB * T1V * DD];
__device__ float g_O[BB * T1V * DD];
__device__ float g_H[BB * T1V * DD];
__device__ float g_S[(long long)BB * T1V * SP1];
__device__ float g_Wr[4][DD * DD];   // tf32-rounded Wq, Wk, Wv, Wo
__device__ float g_M1[BB * DD];
__device__ float g_S1[BB * DD];
__device__ float g_Qn[BB * DD];
__device__ float g_Kp[BB * DD];
__device__ float g_P1[BB * DD];
__device__ float g_TA[BB * DD];
__device__ float g_TB[BB * DD];

// ------------------- helpers -------------------
__device__ __forceinline__ unsigned f2tf(float x) {
    unsigned r;
    asm("cvt.rna.tf32.f32 %0, %1;" : "=r"(r) : "f"(x));
    return r;
}
__device__ __forceinline__ float roundtf(float x) { return __uint_as_float(f2tf(x)); }

__device__ __forceinline__ void mma_tf32(float (&c)[4], unsigned a0, unsigned a1,
                                         unsigned a2, unsigned a3, unsigned b0, unsigned b1) {
    asm volatile(
        "mma.sync.aligned.m16n8k8.row.col.f32.tf32.tf32.f32 "
        "{%0,%1,%2,%3}, {%4,%5,%6,%7}, {%8,%9}, {%0,%1,%2,%3};"
        : "+f"(c[0]), "+f"(c[1]), "+f"(c[2]), "+f"(c[3])
        : "r"(a0), "r"(a1), "r"(a2), "r"(a3), "r"(b0), "r"(b1));
}

__device__ __forceinline__ void cp_async16(float* s, const float* g, int bytes) {
    unsigned saddr = (unsigned)__cvta_generic_to_shared(s);
    asm volatile("cp.async.cg.shared.global [%0], [%1], 16, %2;\n"
                 :: "r"(saddr), "l"(g), "r"(bytes));
}

// ------------------- TF32 tensor-core GEMM -------------------
// C = alpha * A @ op(B) + bias.  A: MxK row-major (pitch lda).
// TRANSB=false: B is KxN (pitch ldb).  TRANSB=true: B is NxK (pitch ldb), C = A@B^T.
// CONV=true: convert fragments to tf32 in inner loop (operands are raw fp32).
// CONV=false: operands must already be tf32-rounded fp32; fragments loaded raw.
// roundOut: round C to tf32 precision before store (for GEMM-chained outputs).
#define APITCH 36
#define BPITCH_NN 136
#define AS_FLOATS (128 * APITCH)
#define BS_FLOATS (128 * APITCH)
#define STAGE_FLOATS (AS_FLOATS + BS_FLOATS)
#define GEMM_SMEM_BYTES (2 * STAGE_FLOATS * 4)   // 73728

template <bool TRANSB, bool CONV>
__global__ __launch_bounds__(256, 2) void gemm_tf32_kernel(
    const float* __restrict__ A, const float* __restrict__ Bm,
    const float* __restrict__ bias, float* __restrict__ C,
    int M, int N, int Kd, float alpha,
    int lda, int ldb, int ldc,
    long long sA, long long sB, long long sC, int roundOut)
{
    A += (long long)blockIdx.z * sA;
    Bm += (long long)blockIdx.z * sB;
    C += (long long)blockIdx.z * sC;

    extern __shared__ float smem[];
    const int tid = threadIdx.x;
    const int warp = tid >> 5;
    const int lane = tid & 31;
    const int warp_m = warp & 1;
    const int warp_n = warp >> 1;
    const int qrow = lane >> 2;
    const int qcol = lane & 3;
    const int m0 = blockIdx.y * 128;
    const int n0 = blockIdx.x * 128;

    float acc[16][4];
#pragma unroll
    for (int i = 0; i < 16; i++)
#pragma unroll
        for (int j = 0; j < 4; j++) acc[i][j] = 0.f;

    const int nk = (Kd + 31) >> 5;

    auto load_tiles = [&](int kt, int buf) {
        float* As = smem + buf * STAGE_FLOATS;
        float* Bs = As + AS_FLOATS;
        int k0 = kt << 5;
#pragma unroll
        for (int c = 0; c < 4; c++) {
            int idx = c * 256 + tid;
            int m = idx >> 3, k4 = (idx & 7) << 2;
            int gm = m0 + m, gk = k0 + k4;
            int rem = Kd - gk;
            int bytes = (gm < M) ? (rem >= 4 ? 16 : (rem > 0 ? rem * 4 : 0)) : 0;
            const float* src = bytes ? (A + (long long)gm * lda + gk) : A;
            cp_async16(As + m * APITCH + k4, src, bytes);
        }
        if (!TRANSB) {
#pragma unroll
            for (int c = 0; c < 4; c++) {
                int idx = c * 256 + tid;
                int k = idx >> 5, n4 = (idx & 31) << 2;
                int gk = k0 + k, gn = n0 + n4;
                int rem = N - gn;
                int bytes = (gk < Kd) ? (rem >= 4 ? 16 : (rem > 0 ? rem * 4 : 0)) : 0;
                const float* src = bytes ? (Bm + (long long)gk * ldb + gn) : Bm;
                cp_async16(Bs + k * BPITCH_NN + n4, src, bytes);
            }
        } else {
#pragma unroll
            for (int c = 0; c < 4; c++) {
                int idx = c * 256 + tid;
                int n = idx >> 3, k4 = (idx & 7) << 2;
                int gn = n0 + n, gk = k0 + k4;
                int rem = Kd - gk;
                int bytes = (gn < N) ? (rem >= 4 ? 16 : (rem > 0 ? rem * 4 : 0)) : 0;
                const float* src = bytes ? (Bm + (long long)gn * ldb + gk) : Bm;
                cp_async16(Bs + n * APITCH + k4, src, bytes);
            }
        }
        asm volatile("cp.async.commit_group;\n");
    };

    load_tiles(0, 0);

    for (int kt = 0; kt < nk; kt++) {
        if (kt + 1 < nk) {
            load_tiles(kt + 1, (kt + 1) & 1);
            asm volatile("cp.async.wait_group 1;\n");
        } else {
            asm volatile("cp.async.wait_group 0;\n");
        }
        __syncthreads();

        const float* As = smem + (kt & 1) * STAGE_FLOATS;
        const float* Bs = As + AS_FLOATS;
        const unsigned* Asu = (const unsigned*)As;
        const unsigned* Bsu = (const unsigned*)Bs;

#pragma unroll
        for (int kk = 0; kk < 32; kk += 8) {
            unsigned af[4][4], bf[4][2];
#pragma unroll
            for (int mt = 0; mt < 4; mt++) {
                int base = (warp_m * 64 + mt * 16 + qrow) * APITCH + kk + qcol;
                if (CONV) {
                    af[mt][0] = f2tf(As[base]);
                    af[mt][1] = f2tf(As[base + 8 * APITCH]);
                    af[mt][2] = f2tf(As[base + 4]);
                    af[mt][3] = f2tf(As[base + 8 * APITCH + 4]);
                } else {
                    af[mt][0] = Asu[base];
                    af[mt][1] = Asu[base + 8 * APITCH];
                    af[mt][2] = Asu[base + 4];
                    af[mt][3] = Asu[base + 8 * APITCH + 4];
                }
            }
#pragma unroll
            for (int nt = 0; nt < 4; nt++) {
                int n = warp_n * 32 + nt * 8 + qrow;
                if (!TRANSB) {
                    int base = (kk + qcol) * BPITCH_NN + n;
                    if (CONV) {
                        bf[nt][0] = f2tf(Bs[base]);
                        bf[nt][1] = f2tf(Bs[base + 4 * BPITCH_NN]);
                    } else {
                        bf[nt][0] = Bsu[base];
                        bf[nt][1] = Bsu[base + 4 * BPITCH_NN];
                    }
                } else {
                    int base = n * APITCH + kk + qcol;
                    if (CONV) {
                        bf[nt][0] = f2tf(Bs[base]);
                        bf[nt][1] = f2tf(Bs[base + 4]);
                    } else {
                        bf[nt][0] = Bsu[base];
                        bf[nt][1] = Bsu[base + 4];
                    }
                }
            }
#pragma unroll
            for (int mt = 0; mt < 4; mt++)
#pragma unroll
                for (int nt = 0; nt < 4; nt++)
                    mma_tf32(acc[mt * 4 + nt], af[mt][0], af[mt][1], af[mt][2], af[mt][3],
                             bf[nt][0], bf[nt][1]);
        }
        __syncthreads();
    }

#pragma unroll
    for (int mt = 0; mt < 4; mt++) {
#pragma unroll
        for (int nt = 0; nt < 4; nt++) {
            float* c = acc[mt * 4 + nt];
            int gm = m0 + warp_m * 64 + mt * 16 + qrow;
            int gn = n0 + warp_n * 32 + nt * 8 + (qcol << 1);
            float bx = 0.f, by = 0.f;
            if (bias && gn < N) { bx = bias[gn]; by = bias[gn + 1]; }
            if (gm < M && gn < N) {
                float x = alpha * c[0] + bx, y = alpha * c[1] + by;
                if (roundOut) { x = roundtf(x); y = roundtf(y); }
                *(float2*)(C + (long long)gm * ldc + gn) = make_float2(x, y);
            }
            if (gm + 8 < M && gn < N) {
                float x = alpha * c[2] + bx, y = alpha * c[3] + by;
                if (roundOut) { x = roundtf(x); y = roundtf(y); }
                *(float2*)(C + (long long)(gm + 8) * ldc + gn) = make_float2(x, y);
            }
        }
    }
}

// ------------------- row softmax (pitched, tf32-rounded output) -------------------
__global__ __launch_bounds__(256) void softmax_rows_kernel(float* __restrict__ S, int Tk, int pitch)
{
    long long row = blockIdx.x;
    float* r = S + row * (long long)pitch;
    int tid = threadIdx.x;
    __shared__ float red[256];

    float v[9];
    int cnt = 0;
    float mx = -1e30f;
    for (int i = tid; i < Tk; i += 256) {
        v[cnt] = r[i];
        mx = fmaxf(mx, v[cnt]);
        cnt++;
    }
    red[tid] = mx;
    __syncthreads();
    for (int s = 128; s > 0; s >>= 1) {
        if (tid < s) red[tid] = fmaxf(red[tid], red[tid + s]);
        __syncthreads();
    }
    mx = red[0];
    __syncthreads();

    float sum = 0.f;
    for (int c = 0; c < cnt; c++) {
        v[c] = __expf(v[c] - mx);
        sum += v[c];
    }
    red[tid] = sum;
    __syncthreads();
    for (int s = 128; s > 0; s >>= 1) {
        if (tid < s) red[tid] += red[tid + s];
        __syncthreads();
    }
    float inv = 1.f / red[0];

    cnt = 0;
    for (int i = tid; i < Tk; i += 256) r[i] = roundtf(v[cnt++] * inv);
}

// ------------------- round weights -------------------
__global__ void round_weights_kernel(const float* __restrict__ Wq, const float* __restrict__ Wk,
                                     const float* __restrict__ Wv, const float* __restrict__ Wo,
                                     float* __restrict__ dst)
{
    int idx = blockIdx.x * blockDim.x + threadIdx.x;
    if (idx >= DD * DD) return;
    dst[idx] = roundtf(Wq[idx]);
    dst[DD * DD + idx] = roundtf(Wk[idx]);
    dst[2 * DD * DD + idx] = roundtf(Wv[idx]);
    dst[3 * DD * DD + idx] = roundtf(Wo[idx]);
}

// ------------------- build inputs (tf32-rounded) -------------------
__global__ void build_x0_kernel(float* __restrict__ X, const float* __restrict__ seg0)
{
    long long idx = (long long)blockIdx.x * blockDim.x + threadIdx.x;
    if (idx >= (long long)BB * T0V * DD) return;
    int d = (int)(idx & (DD - 1));
    long long r = idx >> 10;
    int t = (int)(r % T0V);
    int b = (int)(r / T0V);
    float v = 0.f;
    if (t >= 1 && t <= LL) v = seg0[((long long)b * LL + (t - 1)) * DD + d];
    X[idx] = roundtf(v);
}

__global__ void build_xs_kernel(float* __restrict__ X, const float* __restrict__ seg1,
                                const float* __restrict__ prompt)
{
    long long idx = (long long)blockIdx.x * blockDim.x + threadIdx.x;
    if (idx >= (long long)BB * TSV * DD) return;
    int d = (int)(idx & (DD - 1));
    long long r = idx >> 10;
    int t = (int)(r % TSV);
    int b = (int)(r / TSV);
    float v;
    if (t == 0 || t == TSV - 1) v = prompt[d];
    else v = seg1[((long long)b * LL + (t - 1)) * DD + d];
    X[idx] = roundtf(v);
}

__global__ void build_x1_kernel(float* __restrict__ X, const float* __restrict__ seg0,
                                const float* __restrict__ seg1, const float* __restrict__ P1)
{
    long long idx = (long long)blockIdx.x * blockDim.x + threadIdx.x;
    if (idx >= (long long)BB * T1V * DD) return;
    int d = (int)(idx & (DD - 1));
    long long r = idx >> 10;
    int t = (int)(r % T1V);
    int b = (int)(r / T1V);
    float v;
    if (t < KS) v = seg0[((long long)b * LL + (LL - KS + t)) * DD + d];
    else if (t == KS || t == T1V - 1) v = P1[b * DD + d];
    else v = seg1[((long long)b * LL + (t - KS - 1)) * DD + d];
    X[idx] = roundtf(v);
}

__global__ void gather_q_kernel(float* __restrict__ dst, const float* __restrict__ seg1)
{
    int idx = blockIdx.x * blockDim.x + threadIdx.x;
    if (idx >= BB * DD) return;
    int d = idx & (DD - 1);
    int b = idx >> 10;
    dst[idx] = roundtf(seg1[((long long)b * LL + (JJ - 1)) * DD + d]);
}

__global__ void copy_rows_kernel(float* __restrict__ dst, const float* __restrict__ H,
                                 int T, int t_begin, int rows)
{
    long long idx = (long long)blockIdx.x * blockDim.x + threadIdx.x;
    if (idx >= (long long)BB * rows * DD) return;
    int d = (int)(idx & (DD - 1));
    long long r = idx >> 10;
    int t = (int)(r % rows);
    int b = (int)(r / rows);
    dst[idx] = H[((long long)b * T + t_begin + t) * DD + d];
}

// ------------------- summarize attention -------------------
__global__ __launch_bounds__(256) void summ_attn_kernel(
    const float* __restrict__ Qrow, const float* __restrict__ Ksm,
    const float* __restrict__ Vsm, float* __restrict__ out, int T)
{
    int b = blockIdx.x;
    const float* q = Qrow + b * DD;
    const float* Kb = Ksm + (long long)b * T * DD;
    const float* Vb = Vsm + (long long)b * T * DD;
    __shared__ float sc[TSV];
    __shared__ float red[256];
    int tid = threadIdx.x;
    int lane = tid & 31, warp = tid >> 5;

    for (int j = warp; j < T; j += 8) {
        float s = 0.f;
        const float* kr = Kb + (long long)j * DD;
        for (int d = lane; d < DD; d += 32) s += q[d] * kr[d];
        for (int o = 16; o > 0; o >>= 1) s += __shfl_xor_sync(0xFFFFFFFFu, s, o);
        if (lane == 0) sc[j] = s * SCALE;
    }
    __syncthreads();

    float mx = -1e30f;
    for (int i = tid; i < T; i += 256) mx = fmaxf(mx, sc[i]);
    red[tid] = mx;
    __syncthreads();
    for (int s = 128; s > 0; s >>= 1) {
        if (tid < s) red[tid] = fmaxf(red[tid], red[tid + s]);
        __syncthreads();
    }
    mx = red[0];
    __syncthreads();

    float sum = 0.f;
    for (int i = tid; i < T; i += 256) {
        float e = __expf(sc[i] - mx);
        sc[i] = e;
        sum += e;
    }
    red[tid] = sum;
    __syncthreads();
    for (int s = 128; s > 0; s >>= 1) {
        if (tid < s) red[tid] += red[tid + s];
        __syncthreads();
    }
    float inv = 1.f / red[0];
    __syncthreads();
    for (int i = tid; i < T; i += 256) sc[i] *= inv;
    __syncthreads();

    for (int d = tid; d < DD; d += 256) {
        float acc = 0.f;
        for (int j = 0; j < T; j++) acc = fmaf(sc[j], Vb[(long long)j * DD + d], acc);
        out[b * DD + d] = acc;
    }
}

// ------------------- memory attention -------------------
__global__ __launch_bounds__(256) void mem_attn_kernel(
    const float* __restrict__ Qn, const float* __restrict__ Kp,
    const float* __restrict__ M1, float* __restrict__ P1)
{
    __shared__ float sc[BB][BB];
    int tid = threadIdx.x;
    int lane = tid & 31, warp = tid >> 5;

    for (int j = 0; j < BB; j++) {
        float s = 0.f;
        for (int d = lane; d < DD; d += 32) s += Qn[warp * DD + d] * Kp[j * DD + d];
        for (int o = 16; o > 0; o >>= 1) s += __shfl_xor_sync(0xFFFFFFFFu, s, o);
        if (lane == 0) sc[warp][j] = s * SCALE;
    }
    __syncthreads();

    if (tid < BB) {
        float mx = -1e30f;
        for (int j = 0; j < BB; j++) mx = fmaxf(mx, sc[tid][j]);
        float sum = 0.f;
        for (int j = 0; j < BB; j++) {
            float e = __expf(sc[tid][j] - mx);
            sc[tid][j] = e;
            sum += e;
        }
        float inv = 1.f / sum;
        for (int j = 0; j < BB; j++) sc[tid][j] *= inv;
    }
    __syncthreads();

    for (int idx = tid; idx < BB * DD; idx += 256) {
        int b = idx >> 10, d = idx & (DD - 1);
        float acc = 0.f;
        for (int j = 0; j < BB; j++) acc = fmaf(sc[b][j], M1[j * DD + d], acc);
        P1[idx] = acc;
    }
}

// ------------------- host orchestration -------------------
static inline void gemm(const float* A, const float* Bm, const float* bias, float* C,
                        int M, int N, int Kd, float alpha, int batch,
                        long long sA, long long sB, long long sC, bool transB,
                        int lda, int ldb, int ldc, bool conv, int roundOut)
{
    dim3 grid((N + 127) / 128, (M + 127) / 128, batch);
    if (transB) {
        if (conv) {
            cudaFuncSetAttribute(gemm_tf32_kernel<true, true>,
                                 cudaFuncAttributeMaxDynamicSharedMemorySize, GEMM_SMEM_BYTES);
            gemm_tf32_kernel<true, true><<<grid, 256, GEMM_SMEM_BYTES>>>(
                A, Bm, bias, C, M, N, Kd, alpha, lda, ldb, ldc, sA, sB, sC, roundOut);
        } else {
            cudaFuncSetAttribute(gemm_tf32_kernel<true, false>,
                                 cudaFuncAttributeMaxDynamicSharedMemorySize, GEMM_SMEM_BYTES);
            gemm_tf32_kernel<true, false><<<grid, 256, GEMM_SMEM_BYTES>>>(
                A, Bm, bias, C, M, N, Kd, alpha, lda, ldb, ldc, sA, sB, sC, roundOut);
        }
    } else {
        if (conv) {
            cudaFuncSetAttribute(gemm_tf32_kernel<false, true>,
                                 cudaFuncAttributeMaxDynamicSharedMemorySize, GEMM_SMEM_BYTES);
            gemm_tf32_kernel<false, true><<<grid, 256, GEMM_SMEM_BYTES>>>(
                A, Bm, bias, C, M, N, Kd, alpha, lda, ldb, ldc, sA, sB, sC, roundOut);
        } else {
            cudaFuncSetAttribute(gemm_tf32_kernel<false, false>,
                                 cudaFuncAttributeMaxDynamicSharedMemorySize, GEMM_SMEM_BYTES);
            gemm_tf32_kernel<false, false><<<grid, 256, GEMM_SMEM_BYTES>>>(
                A, Bm, bias, C, M, N, Kd, alpha, lda, ldb, ldc, sA, sB, sC, roundOut);
        }
    }
}

extern "C" void kernel_launch(void* const* d_in, const int* in_sizes, int n_in,
                              void* d_out, int out_size)
{
    const float* seg0   = (const float*)d_in[0];
    const float* seg1   = (const float*)d_in[1];
    const float* prompt = (const float*)d_in[2];
    const float* Wq_mem = (const float*)d_in[3];
    const float* bq_mem = (const float*)d_in[4];
    const float* Wk_mem = (const float*)d_in[5];
    const float* bk_mem = (const float*)d_in[6];
    const float* Wq     = (const float*)d_in[7];
    const float* bq     = (const float*)d_in[8];
    const float* Wk     = (const float*)d_in[9];
    const float* bk     = (const float*)d_in[10];
    const float* Wv     = (const float*)d_in[11];
    const float* bv     = (const float*)d_in[12];
    const float* Wo     = (const float*)d_in[13];
    const float* bo     = (const float*)d_in[14];
    float* out = (float*)d_out;

    float *pX, *pQ, *pK, *pV, *pO, *pH, *pS, *pWr;
    float *pM1, *pS1, *pQn, *pKp, *pP1, *pTA, *pTB;
    cudaGetSymbolAddress((void**)&pX, g_X);
    cudaGetSymbolAddress((void**)&pQ, g_Q);
    cudaGetSymbolAddress((void**)&pK, g_K);
    cudaGetSymbolAddress((void**)&pV, g_V);
    cudaGetSymbolAddress((void**)&pO, g_O);
    cudaGetSymbolAddress((void**)&pH, g_H);
    cudaGetSymbolAddress((void**)&pS, g_S);
    cudaGetSymbolAddress((void**)&pWr, g_Wr);
    cudaGetSymbolAddress((void**)&pM1, g_M1);
    cudaGetSymbolAddress((void**)&pS1, g_S1);
    cudaGetSymbolAddress((void**)&pQn, g_Qn);
    cudaGetSymbolAddress((void**)&pKp, g_Kp);
    cudaGetSymbolAddress((void**)&pP1, g_P1);
    cudaGetSymbolAddress((void**)&pTA, g_TA);
    cudaGetSymbolAddress((void**)&pTB, g_TB);

    const float* Wq_r = pWr;
    const float* Wk_r = pWr + DD * DD;
    const float* Wv_r = pWr + 2 * DD * DD;
    const float* Wo_r = pWr + 3 * DD * DD;

    const int nthr = 256;

    // round the 4 backbone weight matrices once
    round_weights_kernel<<<(DD * DD + nthr - 1) / nthr, nthr>>>(Wq, Wk, Wv, Wo, pWr);

    // ---------------- Phase 0: backbone over [0, seg0, 0], T = 2050 ----------------
    {
        long long n = (long long)BB * T0V * DD;
        build_x0_kernel<<<(int)((n + nthr - 1) / nthr), nthr>>>(pX, seg0);

        int M = BB * T0V;
        gemm(pX, Wq_r, bq, pQ, M, DD, DD, 1.f, 1, 0, 0, 0, false, DD, DD, DD, false, 1);
        gemm(pX, Wk_r, bk, pK, M, DD, DD, 1.f, 1, 0, 0, 0, false, DD, DD, DD, false, 1);
        gemm(pX, Wv_r, bv, pV, M, DD, DD, 1.f, 1, 0, 0, 0, false, DD, DD, DD, false, 1);

        gemm(pQ, pK, nullptr, pS, T0V, T0V, DD, SCALE, BB,
             (long long)T0V * DD, (long long)T0V * DD, (long long)T0V * SP0, true,
             DD, DD, SP0, false, 0);
        softmax_rows_kernel<<<BB * T0V, 256>>>(pS, T0V, SP0);
        gemm(pS, pV, nullptr, pO, T0V, DD, T0V, 1.f, BB,
             (long long)T0V * SP0, (long long)T0V * DD, (long long)T0V * DD, false,
             SP0, DD, DD, false, 1);
        gemm(pO, Wo_r, bo, pH, M, DD, DD, 1.f, 1, 0, 0, 0, false, DD, DD, DD, false, 0);

        long long n0 = (long long)BB * OUT0_ROWS * DD;
        copy_rows_kernel<<<(int)((n0 + nthr - 1) / nthr), nthr>>>(out, pH, T0V, KS + 1, OUT0_ROWS);
        copy_rows_kernel<<<(BB * DD + nthr - 1) / nthr, nthr>>>(pM1, pH, T0V, T0V - 1, 1);
    }

    // ---------------- Summarize(seg1): T = 514 ----------------
    {
        long long n = (long long)BB * TSV * DD;
        build_xs_kernel<<<(int)((n + nthr - 1) / nthr), nthr>>>(pX, seg1, prompt);

        int M = BB * TSV;
        gemm(pX, Wk_r, bk, pK, M, DD, DD, 1.f, 1, 0, 0, 0, false, DD, DD, DD, false, 0);
        gemm(pX, Wv_r, bv, pV, M, DD, DD, 1.f, 1, 0, 0, 0, false, DD, DD, DD, false, 0);

        gather_q_kernel<<<(BB * DD + nthr - 1) / nthr, nthr>>>(pTA, seg1);
        gemm(pTA, Wq_r, bq, pTB, BB, DD, DD, 1.f, 1, 0, 0, 0, false, DD, DD, DD, false, 0);

        summ_attn_kernel<<<BB, 256>>>(pTB, pK, pV, pTA, TSV);
        gemm(pTA, Wo, bo, pS1, BB, DD, DD, 1.f, 1, 0, 0, 0, false, DD, DD, DD, true, 0);
    }

    // ---------------- Memory attention ----------------
    {
        gemm(pS1, Wq_mem, bq_mem, pQn, BB, DD, DD, 1.f, 1, 0, 0, 0, false, DD, DD, DD, true, 0);
        gemm(pM1, Wk_mem, bk_mem, pKp, BB, DD, DD, 1.f, 1, 0, 0, 0, false, DD, DD, DD, true, 0);
        mem_attn_kernel<<<1, 256>>>(pQn, pKp, pM1, pP1);
    }

    // ---------------- Phase 1: backbone over [sensory, P1, seg1, P1], T = 2082 ----------------
    {
        long long n = (long long)BB * T1V * DD;
        build_x1_kernel<<<(int)((n + nthr - 1) / nthr), nthr>>>(pX, seg0, seg1, pP1);

        int M = BB * T1V;
        gemm(pX, Wq_r, bq, pQ, M, DD, DD, 1.f, 1, 0, 0, 0, false, DD, DD, DD, false, 1);
        gemm(pX, Wk_r, bk, pK, M, DD, DD, 1.f, 1, 0, 0, 0, false, DD, DD, DD, false, 1);
        gemm(pX, Wv_r, bv, pV, M, DD, DD, 1.f, 1, 0, 0, 0, false, DD, DD, DD, false, 1);

        gemm(pQ, pK, nullptr, pS, T1V, T1V, DD, SCALE, BB,
             (long long)T1V * DD, (long long)T1V * DD, (long long)T1V * SP1, true,
             DD, DD, SP1, false, 0);
        softmax_rows_kernel<<<BB * T1V, 256>>>(pS, T1V, SP1);
        gemm(pS, pV, nullptr, pO, T1V, DD, T1V, 1.f, BB,
             (long long)T1V * SP1, (long long)T1V * DD, (long long)T1V * DD, false,
             SP1, DD, DD, false, 1);
        gemm(pO, Wo_r, bo, pH, M, DD, DD, 1.f, 1, 0, 0, 0, false, DD, DD, DD, false, 0);

        long long n1 = (long long)BB * OUT1_ROWS * DD;
        copy_rows_kernel<<<(int)((n1 + nthr - 1) / nthr), nthr>>>(out + OFF1, pH, T1V, KS + 1, OUT1_ROWS);
    }
}